// round 1
// baseline (speedup 1.0000x reference)
#include <cuda_runtime.h>
#include <cstdint>

#define NN 100000
#define NE 1600000
#define NF 128
#define NG 64
#define KI 5
#define ALPHA 0.1f

#define NB_NODES ((NN + 255) / 256)   // 391 blocks of 256 covering nodes

// ---- scratch (__device__ globals; no allocation allowed) ----
__device__ int   g_deg[NN];
__device__ int   g_rowoff[NN + 1];
__device__ int   g_cursor[NN];
__device__ int   g_bsum[512];
__device__ int   g_csr_src[NE];        // 6.4 MB
__device__ float g_gate_e[NN];
__device__ float g_gate[NN];
__device__ float g_ssum[KI * NG];

// ------------------------------------------------------------------
// setup: zero scratch
__global__ void k_zero() {
    int i = blockIdx.x * blockDim.x + threadIdx.x;
    if (i < NN) g_deg[i] = 0;
    if (i < KI * NG) g_ssum[i] = 0.0f;
}

// histogram of in-degrees
__global__ void k_hist(const int* __restrict__ dst) {
    int e = blockIdx.x * blockDim.x + threadIdx.x;
    if (e < NE) atomicAdd(&g_deg[dst[e]], 1);
}

// block-local exclusive scan of degrees
__global__ void k_scan1() {
    __shared__ int s[256];
    int n = blockIdx.x * 256 + threadIdx.x;
    int v = (n < NN) ? g_deg[n] : 0;
    s[threadIdx.x] = v;
    __syncthreads();
    for (int off = 1; off < 256; off <<= 1) {
        int t = (threadIdx.x >= off) ? s[threadIdx.x - off] : 0;
        __syncthreads();
        s[threadIdx.x] += t;
        __syncthreads();
    }
    if (n < NN) g_rowoff[n] = s[threadIdx.x] - v;   // exclusive
    if (threadIdx.x == 255) g_bsum[blockIdx.x] = s[255];
}

// scan block sums (single block; NB_NODES = 391 <= 512)
__global__ void k_scan2() {
    __shared__ int s[512];
    int v = (threadIdx.x < NB_NODES) ? g_bsum[threadIdx.x] : 0;
    s[threadIdx.x] = v;
    __syncthreads();
    for (int off = 1; off < 512; off <<= 1) {
        int t = (threadIdx.x >= off) ? s[threadIdx.x - off] : 0;
        __syncthreads();
        s[threadIdx.x] += t;
        __syncthreads();
    }
    if (threadIdx.x < NB_NODES) g_bsum[threadIdx.x] = s[threadIdx.x] - v;  // exclusive
}

// add block offsets; init cursor; cap row offsets
__global__ void k_scan3() {
    int n = blockIdx.x * 256 + threadIdx.x;
    if (n < NN) {
        int r = g_rowoff[n] + g_bsum[blockIdx.x];
        g_rowoff[n] = r;
        g_cursor[n] = r;
    }
    if (n == 0) g_rowoff[NN] = NE;
}

// scatter edges into CSR-by-dst
__global__ void k_scatter(const int* __restrict__ src, const int* __restrict__ dst) {
    int e = blockIdx.x * blockDim.x + threadIdx.x;
    if (e < NE) {
        int pos = atomicAdd(&g_cursor[dst[e]], 1);
        g_csr_src[pos] = src[e];
    }
}

// ------------------------------------------------------------------
// gate: one warp per node. gate_e = exp(feat . W_i + b_i); segment-sum per graph.
// (max-subtraction skipped: mathematically cancels in the softmax ratio, and the
//  gate magnitudes here are O(1) so exp cannot overflow.)
__global__ void k_gate(const float* __restrict__ feat,
                       const float* __restrict__ W,   // W + i*NF
                       const float* __restrict__ b, int it,
                       const int* __restrict__ gid) {
    int warp = (blockIdx.x * blockDim.x + threadIdx.x) >> 5;
    int lane = threadIdx.x & 31;
    if (warp >= NN) return;
    float4 w = *reinterpret_cast<const float4*>(W + lane * 4);
    float4 f = *reinterpret_cast<const float4*>(feat + (size_t)warp * NF + lane * 4);
    float d = f.x * w.x + f.y * w.y + f.z * w.z + f.w * w.w;
    #pragma unroll
    for (int o = 16; o; o >>= 1) d += __shfl_xor_sync(0xFFFFFFFFu, d, o);
    if (lane == 0) {
        float e = expf(d + b[it]);
        g_gate_e[warp] = e;
        atomicAdd(&g_ssum[it * NG + gid[warp]], e);   // compiles to RED, 320 hot slots
    }
}

// normalize: gate = gate_e / segsum
__global__ void k_norm(const int* __restrict__ gid, int it) {
    int n = blockIdx.x * blockDim.x + threadIdx.x;
    if (n < NN) g_gate[n] = g_gate_e[n] / g_ssum[it * NG + gid[n]];
}

// gather + alpha-blend epilogue: one warp per node, lane owns one float4 of the row.
// out[n] = (1-ALPHA) * sum_{s in in(n)} gate[s]*feat[s] + ALPHA * feat0[n]
__global__ void __launch_bounds__(256) k_gather(const float* __restrict__ feat,
                                                const float* __restrict__ feat0,
                                                float* __restrict__ out) {
    int warp = (blockIdx.x * blockDim.x + threadIdx.x) >> 5;
    int lane = threadIdx.x & 31;
    if (warp >= NN) return;
    int beg = g_rowoff[warp];
    int end = g_rowoff[warp + 1];
    float4 acc = make_float4(0.f, 0.f, 0.f, 0.f);
    for (int k = beg; k < end; k++) {
        int s = g_csr_src[k];
        float g = g_gate[s];
        float4 f = *reinterpret_cast<const float4*>(feat + (size_t)s * NF + lane * 4);
        acc.x += f.x * g;
        acc.y += f.y * g;
        acc.z += f.z * g;
        acc.w += f.w * g;
    }
    float4 f0 = __ldcs(reinterpret_cast<const float4*>(feat0 + (size_t)warp * NF + lane * 4));
    float4 o;
    o.x = (1.0f - ALPHA) * acc.x + ALPHA * f0.x;
    o.y = (1.0f - ALPHA) * acc.y + ALPHA * f0.y;
    o.z = (1.0f - ALPHA) * acc.z + ALPHA * f0.z;
    o.w = (1.0f - ALPHA) * acc.w + ALPHA * f0.w;
    *reinterpret_cast<float4*>(out + (size_t)warp * NF + lane * 4) = o;
}

// ------------------------------------------------------------------
extern "C" void kernel_launch(void* const* d_in, const int* in_sizes, int n_in,
                              void* d_out, int out_size) {
    const float* feat = (const float*)d_in[0];   // [NN, NF]
    const float* W    = (const float*)d_in[1];   // [KI, NF]
    const float* b    = (const float*)d_in[2];   // [KI]
    const int*   src  = (const int*)d_in[3];     // [NE] (JAX int64 request -> int32)
    const int*   dst  = (const int*)d_in[4];     // [NE]
    const int*   gid  = (const int*)d_in[5];     // [NN]
    float* out = (float*)d_out;                  // [KI, NN, NF]

    const int EB = (NE + 255) / 256;

    // CSR-by-dst build (once per launch)
    k_zero<<<NB_NODES, 256>>>();
    k_hist<<<EB, 256>>>(dst);
    k_scan1<<<NB_NODES, 256>>>();
    k_scan2<<<1, 512>>>();
    k_scan3<<<NB_NODES, 256>>>();
    k_scatter<<<EB, 256>>>(src, dst);

    const int NODE_WARP_BLOCKS = (NN * 32 + 255) / 256;  // 12500
    const float* fin = feat;
    for (int i = 0; i < KI; i++) {
        k_gate<<<NODE_WARP_BLOCKS, 256>>>(fin, W + i * NF, b, i, gid);
        k_norm<<<NB_NODES, 256>>>(gid, i);
        float* oi = out + (size_t)i * NN * NF;
        k_gather<<<NODE_WARP_BLOCKS, 256>>>(fin, feat, oi);
        fin = oi;
    }
}

// round 4
// speedup vs baseline: 1.1923x; 1.1923x over previous
#include <cuda_runtime.h>
#include <cstdint>

#define NN 100000
#define NE 1600000
#define NF 128
#define NG 64
#define KI 5
#define ALPHA 0.1f

#define NB_NODES ((NN + 255) / 256)   // 391 blocks of 256 covering nodes

// ---- scratch (__device__ globals; no allocation allowed) ----
__device__ int   g_deg[NN];
__device__ int   g_rowoff[NN + 1];
__device__ int   g_cursor[NN];
__device__ int   g_bsum[512];
__device__ int   g_csr_src[NE];        // 6.4 MB
__device__ float g_gate_e[NN];
__device__ float g_gate[NN];
__device__ float g_ssum[KI * NG];

// ------------------------------------------------------------------
// setup: zero scratch
__global__ void k_zero() {
    int i = blockIdx.x * blockDim.x + threadIdx.x;
    if (i < NN) g_deg[i] = 0;
    if (i < KI * NG) g_ssum[i] = 0.0f;
}

// histogram of in-degrees (4 edges/thread via int4)
__global__ void k_hist(const int4* __restrict__ dst4) {
    int e = blockIdx.x * blockDim.x + threadIdx.x;
    if (e < NE / 4) {
        int4 d = dst4[e];
        atomicAdd(&g_deg[d.x], 1);
        atomicAdd(&g_deg[d.y], 1);
        atomicAdd(&g_deg[d.z], 1);
        atomicAdd(&g_deg[d.w], 1);
    }
}

// block-local exclusive scan of degrees
__global__ void k_scan1() {
    __shared__ int s[256];
    int n = blockIdx.x * 256 + threadIdx.x;
    int v = (n < NN) ? g_deg[n] : 0;
    s[threadIdx.x] = v;
    __syncthreads();
    for (int off = 1; off < 256; off <<= 1) {
        int t = (threadIdx.x >= off) ? s[threadIdx.x - off] : 0;
        __syncthreads();
        s[threadIdx.x] += t;
        __syncthreads();
    }
    if (n < NN) g_rowoff[n] = s[threadIdx.x] - v;   // exclusive
    if (threadIdx.x == 255) g_bsum[blockIdx.x] = s[255];
}

// scan block sums (single block; NB_NODES = 391 <= 512)
__global__ void k_scan2() {
    __shared__ int s[512];
    int v = (threadIdx.x < NB_NODES) ? g_bsum[threadIdx.x] : 0;
    s[threadIdx.x] = v;
    __syncthreads();
    for (int off = 1; off < 512; off <<= 1) {
        int t = (threadIdx.x >= off) ? s[threadIdx.x - off] : 0;
        __syncthreads();
        s[threadIdx.x] += t;
        __syncthreads();
    }
    if (threadIdx.x < NB_NODES) g_bsum[threadIdx.x] = s[threadIdx.x] - v;  // exclusive
}

// add block offsets; init cursor; cap row offsets
__global__ void k_scan3() {
    int n = blockIdx.x * 256 + threadIdx.x;
    if (n < NN) {
        int r = g_rowoff[n] + g_bsum[blockIdx.x];
        g_rowoff[n] = r;
        g_cursor[n] = r;
    }
    if (n == 0) g_rowoff[NN] = NE;
}

// scatter edges into CSR-by-dst (4 edges/thread)
__global__ void k_scatter(const int4* __restrict__ src4, const int4* __restrict__ dst4) {
    int e = blockIdx.x * blockDim.x + threadIdx.x;
    if (e < NE / 4) {
        int4 s = src4[e];
        int4 d = dst4[e];
        g_csr_src[atomicAdd(&g_cursor[d.x], 1)] = s.x;
        g_csr_src[atomicAdd(&g_cursor[d.y], 1)] = s.y;
        g_csr_src[atomicAdd(&g_cursor[d.z], 1)] = s.z;
        g_csr_src[atomicAdd(&g_cursor[d.w], 1)] = s.w;
    }
}

// ------------------------------------------------------------------
// gate for iteration 0 only (later gates are fused into the gather epilogue).
__global__ void k_gate0(const float* __restrict__ feat,
                        const float* __restrict__ W,
                        const float* __restrict__ b,
                        const int* __restrict__ gid) {
    int warp = (blockIdx.x * blockDim.x + threadIdx.x) >> 5;
    int lane = threadIdx.x & 31;
    if (warp >= NN) return;
    float4 w = *reinterpret_cast<const float4*>(W + lane * 4);
    float4 f = *reinterpret_cast<const float4*>(feat + (size_t)warp * NF + lane * 4);
    float d = f.x * w.x + f.y * w.y + f.z * w.z + f.w * w.w;
    #pragma unroll
    for (int o = 16; o; o >>= 1) d += __shfl_xor_sync(0xFFFFFFFFu, d, o);
    if (lane == 0) {
        float e = __expf(d + b[0]);
        g_gate_e[warp] = e;
        atomicAdd(&g_ssum[gid[warp]], e);
    }
}

// normalize: gate = gate_e / segsum[iteration it]
__global__ void k_norm(const int* __restrict__ gid, int it) {
    int n = blockIdx.x * blockDim.x + threadIdx.x;
    if (n < NN) g_gate[n] = g_gate_e[n] / g_ssum[it * NG + gid[n]];
}

// gather + alpha-blend + (fused) next-iteration gate.
// out[n] = (1-ALPHA) * sum_{s in in(n)} gate[s]*feat[s] + ALPHA * feat0[n]
// if GATE: gate_e[n] = exp(out[n] . W_next + b[it_next]); atomic segsum.
// 2-way unrolled edge loop: two independent 512B row fetches in flight.
template<bool GATE>
__global__ void __launch_bounds__(256) k_gather(const float* __restrict__ feat,
                                                const float* __restrict__ feat0,
                                                float* __restrict__ out,
                                                const float* __restrict__ W_next,
                                                const float* __restrict__ b,
                                                int it_next,
                                                const int* __restrict__ gid) {
    int warp = (blockIdx.x * blockDim.x + threadIdx.x) >> 5;
    int lane = threadIdx.x & 31;
    if (warp >= NN) return;
    int beg = g_rowoff[warp];
    int end = g_rowoff[warp + 1];
    float4 acc0 = make_float4(0.f, 0.f, 0.f, 0.f);
    float4 acc1 = make_float4(0.f, 0.f, 0.f, 0.f);

    int k = beg;
    // pairs: two rows fetched concurrently into independent accumulators
    for (; k + 1 < end; k += 2) {
        int s0 = g_csr_src[k];
        int s1 = g_csr_src[k + 1];
        float g0 = g_gate[s0];
        float g1 = g_gate[s1];
        float4 f0v = *reinterpret_cast<const float4*>(feat + (size_t)s0 * NF + lane * 4);
        float4 f1v = *reinterpret_cast<const float4*>(feat + (size_t)s1 * NF + lane * 4);
        acc0.x += f0v.x * g0; acc0.y += f0v.y * g0;
        acc0.z += f0v.z * g0; acc0.w += f0v.w * g0;
        acc1.x += f1v.x * g1; acc1.y += f1v.y * g1;
        acc1.z += f1v.z * g1; acc1.w += f1v.w * g1;
    }
    if (k < end) {
        int s0 = g_csr_src[k];
        float g0 = g_gate[s0];
        float4 f0v = *reinterpret_cast<const float4*>(feat + (size_t)s0 * NF + lane * 4);
        acc0.x += f0v.x * g0; acc0.y += f0v.y * g0;
        acc0.z += f0v.z * g0; acc0.w += f0v.w * g0;
    }
    acc0.x += acc1.x; acc0.y += acc1.y; acc0.z += acc1.z; acc0.w += acc1.w;

    float4 f0 = *reinterpret_cast<const float4*>(feat0 + (size_t)warp * NF + lane * 4);
    float4 o;
    o.x = (1.0f - ALPHA) * acc0.x + ALPHA * f0.x;
    o.y = (1.0f - ALPHA) * acc0.y + ALPHA * f0.y;
    o.z = (1.0f - ALPHA) * acc0.z + ALPHA * f0.z;
    o.w = (1.0f - ALPHA) * acc0.w + ALPHA * f0.w;
    *reinterpret_cast<float4*>(out + (size_t)warp * NF + lane * 4) = o;

    if (GATE) {
        float4 w = *reinterpret_cast<const float4*>(W_next + lane * 4);
        float d = o.x * w.x + o.y * w.y + o.z * w.z + o.w * w.w;
        #pragma unroll
        for (int off = 16; off; off >>= 1) d += __shfl_xor_sync(0xFFFFFFFFu, d, off);
        if (lane == 0) {
            float e = __expf(d + b[it_next]);
            g_gate_e[warp] = e;
            atomicAdd(&g_ssum[it_next * NG + gid[warp]], e);
        }
    }
}

// ------------------------------------------------------------------
extern "C" void kernel_launch(void* const* d_in, const int* in_sizes, int n_in,
                              void* d_out, int out_size) {
    const float* feat = (const float*)d_in[0];   // [NN, NF]
    const float* W    = (const float*)d_in[1];   // [KI, NF]
    const float* b    = (const float*)d_in[2];   // [KI]
    const int*   src  = (const int*)d_in[3];     // [NE] (JAX int64 request -> int32)
    const int*   dst  = (const int*)d_in[4];     // [NE]
    const int*   gid  = (const int*)d_in[5];     // [NN]
    float* out = (float*)d_out;                  // [KI, NN, NF]

    const int EB4 = (NE / 4 + 255) / 256;

    // CSR-by-dst build (once per launch)
    k_zero<<<NB_NODES, 256>>>();
    k_hist<<<EB4, 256>>>((const int4*)dst);
    k_scan1<<<NB_NODES, 256>>>();
    k_scan2<<<1, 512>>>();
    k_scan3<<<NB_NODES, 256>>>();
    k_scatter<<<EB4, 256>>>((const int4*)src, (const int4*)dst);

    const int NODE_WARP_BLOCKS = (NN * 32 + 255) / 256;  // 12500

    // gate for iteration 0
    k_gate0<<<NODE_WARP_BLOCKS, 256>>>(feat, W, b, gid);

    const float* fin = feat;
    for (int i = 0; i < KI; i++) {
        k_norm<<<NB_NODES, 256>>>(gid, i);
        float* oi = out + (size_t)i * NN * NF;
        if (i + 1 < KI) {
            k_gather<true><<<NODE_WARP_BLOCKS, 256>>>(fin, feat, oi,
                                                      W + (i + 1) * NF, b, i + 1, gid);
        } else {
            k_gather<false><<<NODE_WARP_BLOCKS, 256>>>(fin, feat, oi,
                                                       nullptr, b, 0, gid);
        }
        fin = oi;
    }
}